// round 11
// baseline (speedup 1.0000x reference)
#include <cuda_runtime.h>

#define BB 4096
#define TT 2048
#define DIN 5
#define H1 9
#define H2 32
#define OUTL 25
#define DOUT 3
#define PAD 8     // prefetch overrun padding (steps) on both ends
#define DEPTH 4   // x prefetch pipeline depth (TT % DEPTH == 0, DEPTH <= PAD)

// Scratch (device globals — no allocation allowed)
__device__ float g_xT[(size_t)(TT + 2 * PAD) * DIN * BB];   // [t+PAD][k][b]
__device__ float g_y[BB * 2 * H1];                          // [b][18]

// Accurate tanh (stage 2; cost negligible there)
__device__ __forceinline__ float tanh_fast(float a) {
    float t = __expf(a + a);
    return 1.0f - __fdividef(2.0f, t + 1.0f);
}

// Hardware tanh (MUFU.TANH): 1 op, ~16 cyc
__device__ __forceinline__ float tanh_hw(float a) {
    float r;
    asm("tanh.approx.f32 %0, %1;" : "=f"(r) : "f"(a));
    return r;
}

// ---- packed f32x2 helpers (FFMA2 only reachable via PTX fma.rn.f32x2) ----
typedef unsigned long long u64t;

__device__ __forceinline__ u64t pack2(float lo, float hi) {
    u64t r;
    asm("mov.b64 %0, {%1, %2};" : "=l"(r) : "f"(lo), "f"(hi));
    return r;
}
__device__ __forceinline__ float2 unpack2(u64t v) {
    float2 f;
    asm("mov.b64 {%0, %1}, %2;" : "=f"(f.x), "=f"(f.y) : "l"(v));
    return f;
}
__device__ __forceinline__ u64t fma2(u64t a, u64t b, u64t c) {   // a*b + c
    u64t d;
    asm("fma.rn.f32x2 %0, %1, %2, %3;" : "=l"(d) : "l"(a), "l"(b), "l"(c));
    return d;
}
__device__ __forceinline__ u64t add2(u64t a, u64t b) {
    u64t d;
    asm("add.rn.f32x2 %0, %1, %2;" : "=l"(d) : "l"(a), "l"(b));
    return d;
}

// ---------------------------------------------------------------------------
// Transpose x [B,T,5] -> g_xT [t+PAD][k][b]   (coalesced both sides)
// grid: (B/32, T/32), block: 256
// ---------------------------------------------------------------------------
__global__ void __launch_bounds__(256) transpose_kernel(const float* __restrict__ x) {
    __shared__ float tile[32][161];
    int b0 = blockIdx.x * 32;
    int t0 = blockIdx.y * 32;
    int tid = threadIdx.x;

    int bl = tid >> 3;      // 0..31
    int l8 = tid & 7;       // 0..7
    const float4* src = (const float4*)(x + ((size_t)(b0 + bl) * TT + t0) * DIN);
#pragma unroll
    for (int it = 0; it < 5; it++) {
        float4 v = src[l8 + it * 8];
        int c = (l8 + it * 8) * 4;
        tile[bl][c + 0] = v.x; tile[bl][c + 1] = v.y;
        tile[bl][c + 2] = v.z; tile[bl][c + 3] = v.w;
    }
    __syncthreads();

    int bw = tid & 31;
    int r0 = tid >> 5;      // 0..7
#pragma unroll
    for (int it = 0; it < 20; it++) {
        int r = r0 + it * 8;            // 0..159
        int tl = r / 5;
        int k  = r - tl * 5;
        g_xT[((size_t)(t0 + tl + PAD) * DIN + k) * BB + b0 + bw] = tile[bw][r];
    }
}

// ---------------------------------------------------------------------------
// Stage 1: bidirectional H1=9 RNN, f32x2-packed over adjacent batch pairs
// (2b, 2b+1). 4096 pairs x 4 lanes (3 units/lane, lane 3 = zero dummies)
// = 16384 threads = 512 warps = 1 warp/SMSP; each step advances 2 sequences.
// x loads are LDG.64 (pair is adjacent in g_xT). DEPTH-deep prefetch ring.
// grid: 128, block: 128
// ---------------------------------------------------------------------------
__global__ void __launch_bounds__(128) rnn1_kernel(
    const float* __restrict__ w_ih_f, const float* __restrict__ w_hh_f,
    const float* __restrict__ b_ih_f, const float* __restrict__ b_hh_f,
    const float* __restrict__ w_ih_b, const float* __restrict__ w_hh_b,
    const float* __restrict__ b_ih_b, const float* __restrict__ b_hh_b)
{
    int tid = blockIdx.x * 128 + threadIdx.x;
    int p   = tid >> 2;           // pair id, 0..4095
    int s   = tid & 3;            // unit slice: units s*3 .. s*3+2 (s=3 dummy)
    int d   = p >> 11;            // 0 = forward, 1 = backward
    int b2  = p & 2047;           // pair covers batch 2*b2, 2*b2+1

    const float* wih = d ? w_ih_b : w_ih_f;
    const float* whh = d ? w_hh_b : w_hh_f;
    const float* bih = d ? b_ih_b : b_ih_f;
    const float* bhh = d ? b_hh_b : b_hh_f;

    // Packed per-lane weights for 3 units (zeros for dummy units >= 9).
    // Each packed weight duplicates the scalar into both halves.
    u64t WiP[3][5], WhP[3][9], biasP[3];
#pragma unroll
    for (int m = 0; m < 3; m++) {
        int u = s * 3 + m;
        bool real = (u < H1);
        float bv = real ? (bih[u] + bhh[u]) : 0.0f;
        biasP[m] = pack2(bv, bv);
#pragma unroll
        for (int k = 0; k < 5; k++) {
            float w = real ? wih[u * DIN + k] : 0.0f;
            WiP[m][k] = pack2(w, w);
        }
#pragma unroll
        for (int j = 0; j < 9; j++) {
            float w = real ? whh[u * H1 + j] : 0.0f;
            WhP[m][j] = pack2(w, w);
        }
    }

    float2 h[3];
#pragma unroll
    for (int m = 0; m < 3; m++) h[m] = make_float2(0.0f, 0.0f);

    const float* xp = g_xT + (size_t)(PAD + (d ? TT - 1 : 0)) * DIN * BB + 2 * b2;
    long stride = d ? -(long)(DIN * BB) : (long)(DIN * BB);

    unsigned gbase = (threadIdx.x & 31) & ~3u;   // first lane of 4-lane group

    // One RNN step for the packed pair using packed x registers xr[5]
    auto step = [&](const u64t* xr) {
        // Gather all 9 hidden units (both halves) from lanes gbase..gbase+2
        u64t ha[9];
#pragma unroll
        for (int j = 0; j < 9; j++) {
            unsigned src = gbase + (unsigned)(j / 3);
            float av = __shfl_sync(0xffffffffu, h[j % 3].x, src);
            float bv = __shfl_sync(0xffffffffu, h[j % 3].y, src);
            ha[j] = pack2(av, bv);
        }

#pragma unroll
        for (int m = 0; m < 3; m++) {
            u64t a1 = biasP[m], a2 = pack2(0.0f, 0.0f), a3 = pack2(0.0f, 0.0f);
#pragma unroll
            for (int j = 0; j < 5; j++) a1 = fma2(WhP[m][j], ha[j], a1);
#pragma unroll
            for (int j = 5; j < 9; j++) a2 = fma2(WhP[m][j], ha[j], a2);
#pragma unroll
            for (int k = 0; k < 5; k++) a3 = fma2(WiP[m][k], xr[k], a3);
            float2 av = unpack2(add2(add2(a1, a3), a2));
            h[m] = make_float2(tanh_hw(av.x), tanh_hw(av.y));
        }
    };

    // DEPTH-deep prefetch ring of packed x pairs (LDG.64 each).
    u64t xb[DEPTH][5];
#pragma unroll
    for (int i = 0; i < DEPTH; i++) {
#pragma unroll
        for (int k = 0; k < 5; k++)
            xb[i][k] = *(const u64t*)(xp + (size_t)k * BB);
        xp += stride;
    }

    for (int t = 0; t < TT; t += DEPTH) {
#pragma unroll
        for (int i = 0; i < DEPTH; i++) {
            step(xb[i]);
#pragma unroll
            for (int k = 0; k < 5; k++)
                xb[i][k] = *(const u64t*)(xp + (size_t)k * BB);   // pad-safe
            xp += stride;
        }
    }

    // Write final hidden for both sequences: y[b][d*9 + u], u = s*3+m
#pragma unroll
    for (int m = 0; m < 3; m++) {
        int u = s * 3 + m;
        if (u < H1) {
            int bA = 2 * b2, bB = 2 * b2 + 1;
            g_y[bA * (2 * H1) + d * H1 + u] = h[m].x;
            g_y[bB * (2 * H1) + d * H1 + u] = h[m].y;
        }
    }
}

// ---------------------------------------------------------------------------
// Stage 2: 25-step H2=32 RNN (input only at t=0) + linear head 32->3.
// One warp per batch element; lane = hidden unit.
// grid: 1024, block: 128  (4096 warps)
// ---------------------------------------------------------------------------
__global__ void __launch_bounds__(128) rnn2_kernel(
    const float* __restrict__ w_ih2, const float* __restrict__ w_hh2,
    const float* __restrict__ b_ih2, const float* __restrict__ b_hh2,
    const float* __restrict__ w_out, const float* __restrict__ b_out,
    float* __restrict__ out)
{
    int warp = (blockIdx.x * blockDim.x + threadIdx.x) >> 5;
    int lane = threadIdx.x & 31;
    int bidx = warp;   // grid sized exactly: 4096 warps

    float Wh[32];
#pragma unroll
    for (int j = 0; j < 32; j++) Wh[j] = w_hh2[lane * 32 + j];
    float bias = b_ih2[lane] + b_hh2[lane];
    float wo0 = w_out[0 * 32 + lane];
    float wo1 = w_out[1 * 32 + lane];
    float wo2 = w_out[2 * 32 + lane];
    float bo0 = b_out[0], bo1 = b_out[1], bo2 = b_out[2];

    // t = 0: h = tanh(Wih2 @ y + bias)   (h0 = 0)
    float acc = bias;
    const float* yrow = g_y + bidx * 18;
#pragma unroll
    for (int k = 0; k < 18; k++) acc = fmaf(w_ih2[lane * 18 + k], yrow[k], acc);
    float h = tanh_fast(acc);

    float* outp = out + (size_t)bidx * OUTL * DOUT;

    for (int t = 0; t < OUTL; t++) {
        float p0 = wo0 * h, p1 = wo1 * h, p2 = wo2 * h;
#pragma unroll
        for (int off = 16; off; off >>= 1) {
            p0 += __shfl_xor_sync(0xffffffffu, p0, off);
            p1 += __shfl_xor_sync(0xffffffffu, p1, off);
            p2 += __shfl_xor_sync(0xffffffffu, p2, off);
        }
        if (lane == 0) {
            outp[t * 3 + 0] = p0 + bo0;
            outp[t * 3 + 1] = p1 + bo1;
            outp[t * 3 + 2] = p2 + bo2;
        }
        if (t < OUTL - 1) {
            float accn = bias;
#pragma unroll
            for (int j = 0; j < 32; j++)
                accn = fmaf(Wh[j], __shfl_sync(0xffffffffu, h, j), accn);
            h = tanh_fast(accn);
        }
    }
}

// ---------------------------------------------------------------------------
extern "C" void kernel_launch(void* const* d_in, const int* in_sizes, int n_in,
                              void* d_out, int out_size)
{
    const float* x      = (const float*)d_in[0];
    const float* w_ih_f = (const float*)d_in[1];
    const float* w_hh_f = (const float*)d_in[2];
    const float* b_ih_f = (const float*)d_in[3];
    const float* b_hh_f = (const float*)d_in[4];
    const float* w_ih_b = (const float*)d_in[5];
    const float* w_hh_b = (const float*)d_in[6];
    const float* b_ih_b = (const float*)d_in[7];
    const float* b_hh_b = (const float*)d_in[8];
    const float* w_ih2  = (const float*)d_in[9];
    const float* w_hh2  = (const float*)d_in[10];
    const float* b_ih2  = (const float*)d_in[11];
    const float* b_hh2  = (const float*)d_in[12];
    const float* w_out  = (const float*)d_in[13];
    const float* b_out  = (const float*)d_in[14];
    float* out = (float*)d_out;

    dim3 tg(BB / 32, TT / 32);
    transpose_kernel<<<tg, 256>>>(x);

    rnn1_kernel<<<128, 128>>>(w_ih_f, w_hh_f, b_ih_f, b_hh_f,
                              w_ih_b, w_hh_b, b_ih_b, b_hh_b);

    rnn2_kernel<<<1024, 128>>>(w_ih2, w_hh2, b_ih2, b_hh2, w_out, b_out, out);
}

// round 14
// speedup vs baseline: 1.5790x; 1.5790x over previous
#include <cuda_runtime.h>

#define BB 4096
#define TT 2048
#define DIN 5
#define H1 9
#define H2 32
#define OUTL 25
#define DOUT 3
#define PAD 8     // prefetch overrun padding (steps) on both ends
#define DEPTH 8   // x prefetch pipeline depth (TT % DEPTH == 0, DEPTH <= PAD)

// Scratch (device globals — no allocation allowed)
__device__ float g_xT[(size_t)(TT + 2 * PAD) * DIN * BB];   // [t+PAD][k][b]
__device__ float g_y[BB * 2 * H1];                          // [b][18]

// Accurate tanh (stage 2; cost negligible there)
__device__ __forceinline__ float tanh_fast(float a) {
    float t = __expf(a + a);
    return 1.0f - __fdividef(2.0f, t + 1.0f);
}

// Hardware tanh (MUFU.TANH): 1 op, ~16 cyc
__device__ __forceinline__ float tanh_hw(float a) {
    float r;
    asm("tanh.approx.f32 %0, %1;" : "=f"(r) : "f"(a));
    return r;
}

// ---------------------------------------------------------------------------
// Transpose x [B,T,5] -> g_xT [t+PAD][k][b]   (coalesced both sides)
// grid: (B/32, T/32), block: 256
// ---------------------------------------------------------------------------
__global__ void __launch_bounds__(256) transpose_kernel(const float* __restrict__ x) {
    __shared__ float tile[32][161];
    int b0 = blockIdx.x * 32;
    int t0 = blockIdx.y * 32;
    int tid = threadIdx.x;

    int bl = tid >> 3;      // 0..31
    int l8 = tid & 7;       // 0..7
    const float4* src = (const float4*)(x + ((size_t)(b0 + bl) * TT + t0) * DIN);
#pragma unroll
    for (int it = 0; it < 5; it++) {
        float4 v = src[l8 + it * 8];
        int c = (l8 + it * 8) * 4;
        tile[bl][c + 0] = v.x; tile[bl][c + 1] = v.y;
        tile[bl][c + 2] = v.z; tile[bl][c + 3] = v.w;
    }
    __syncthreads();

    int bw = tid & 31;
    int r0 = tid >> 5;      // 0..7
#pragma unroll
    for (int it = 0; it < 20; it++) {
        int r = r0 + it * 8;            // 0..159
        int tl = r / 5;
        int k  = r - tl * 5;
        g_xT[((size_t)(t0 + tl + PAD) * DIN + k) * BB + b0 + bw] = tile[bw][r];
    }
}

// ---------------------------------------------------------------------------
// Stage 1: bidirectional H1=9 RNN. 2 lanes per sequence (units 0-4 / 5-8+pad).
// 16384 threads = 512 warps -> 1 warp/SMSP.
// Key change vs best-known: the partner-h shuffle is issued at the END of the
// step (right after tanh) and consumed only in the NEXT step, so at step start
// every operand (h, p, x-ring) is already register-resident and the SHFL/MUFU
// latencies hide under ~140 cyc of independent FMA issue.
// grid: 128, block: 128
// ---------------------------------------------------------------------------
__global__ void __launch_bounds__(128) rnn1_kernel(
    const float* __restrict__ w_ih_f, const float* __restrict__ w_hh_f,
    const float* __restrict__ b_ih_f, const float* __restrict__ b_hh_f,
    const float* __restrict__ w_ih_b, const float* __restrict__ w_hh_b,
    const float* __restrict__ b_ih_b, const float* __restrict__ b_hh_b)
{
    int tid  = blockIdx.x * 128 + threadIdx.x;
    int pair = tid >> 1;          // sequence id, 0..8191
    int par  = tid & 1;           // which unit-half
    int d    = pair >> 12;        // 0 = forward, 1 = backward
    int b    = pair & 4095;

    const float* wih = d ? w_ih_b : w_ih_f;
    const float* whh = d ? w_hh_b : w_hh_f;
    const float* bih = d ? b_ih_b : b_ih_f;
    const float* bhh = d ? b_hh_b : b_hh_f;

    // Per-lane weights. Local h[j] holds unit par*5+j; partner p[j] holds
    // unit (par^1)*5+j. WL/WP are pre-permuted so the loop has no selects.
    float Wi[5][5], WL[5][5], WP[5][5], bias[5];
#pragma unroll
    for (int m = 0; m < 5; m++) {
        int u = par * 5 + m;
        bool real = (u < H1);
        bias[m] = real ? (bih[u] + bhh[u]) : 0.0f;
#pragma unroll
        for (int k = 0; k < 5; k++) Wi[m][k] = real ? wih[u * DIN + k] : 0.0f;
#pragma unroll
        for (int j = 0; j < 5; j++) {
            int lu = par * 5 + j;          // unit in local h[j]
            int pu = (par ^ 1) * 5 + j;    // unit in partner p[j]
            WL[m][j] = (real && lu < H1) ? whh[u * H1 + lu] : 0.0f;
            WP[m][j] = (real && pu < H1) ? whh[u * H1 + pu] : 0.0f;
        }
    }

    float h[5] = {0.f, 0.f, 0.f, 0.f, 0.f};
    float p[5] = {0.f, 0.f, 0.f, 0.f, 0.f};   // partner h (pipelined exchange)

    const float* xp = g_xT + (size_t)(PAD + (d ? TT - 1 : 0)) * DIN * BB + b;
    long stride = d ? -(long)(DIN * BB) : (long)(DIN * BB);

    // One RNN step using x registers xr[5]. p[] holds the partner's hidden
    // state for THIS step (shuffled at the end of the previous step).
    auto step = [&](const float* xr) {
        float a[5];
#pragma unroll
        for (int m = 0; m < 5; m++) {
            // x-term first (operands ready earliest), local-h chained on top,
            // partner-term as a separate short chain, single combine add.
            float c1 = bias[m];
#pragma unroll
            for (int k = 0; k < 5; k++) c1 = fmaf(Wi[m][k], xr[k], c1);
#pragma unroll
            for (int j = 0; j < 5; j++) c1 = fmaf(WL[m][j], h[j], c1);
            float c2 = 0.0f;
#pragma unroll
            for (int j = 0; j < 5; j++) c2 = fmaf(WP[m][j], p[j], c2);
            a[m] = c1 + c2;
        }
#pragma unroll
        for (int m = 0; m < 5; m++) h[m] = tanh_hw(a[m]);
        // Issue next step's exchange immediately; latency hides under the
        // next step's x/local FMA stream.
#pragma unroll
        for (int m = 0; m < 5; m++) p[m] = __shfl_xor_sync(0xffffffffu, h[m], 1);
    };

    // DEPTH-deep prefetch ring: refill of slot i happens right after its
    // consumption -> load->use distance is a full DEPTH steps.
    float xb[DEPTH][5];
#pragma unroll
    for (int i = 0; i < DEPTH; i++) {
#pragma unroll
        for (int k = 0; k < 5; k++) xb[i][k] = xp[(size_t)k * BB];
        xp += stride;
    }

    for (int t = 0; t < TT; t += DEPTH) {
#pragma unroll
        for (int i = 0; i < DEPTH; i++) {
            step(xb[i]);
#pragma unroll
            for (int k = 0; k < 5; k++) xb[i][k] = xp[(size_t)k * BB];  // pad-safe
            xp += stride;
        }
    }

    // Write final hidden: y[b][d*9 + u]
    int base = b * (2 * H1) + d * H1 + par * 5;
#pragma unroll
    for (int m = 0; m < 5; m++) {
        if (par == 0 || m < 4) g_y[base + m] = h[m];
    }
}

// ---------------------------------------------------------------------------
// Stage 2: 25-step H2=32 RNN (input only at t=0) + linear head 32->3.
// One warp per batch element; lane = hidden unit.
// grid: 1024, block: 128  (4096 warps)
// ---------------------------------------------------------------------------
__global__ void __launch_bounds__(128) rnn2_kernel(
    const float* __restrict__ w_ih2, const float* __restrict__ w_hh2,
    const float* __restrict__ b_ih2, const float* __restrict__ b_hh2,
    const float* __restrict__ w_out, const float* __restrict__ b_out,
    float* __restrict__ out)
{
    int warp = (blockIdx.x * blockDim.x + threadIdx.x) >> 5;
    int lane = threadIdx.x & 31;
    int bidx = warp;   // grid sized exactly: 4096 warps

    float Wh[32];
#pragma unroll
    for (int j = 0; j < 32; j++) Wh[j] = w_hh2[lane * 32 + j];
    float bias = b_ih2[lane] + b_hh2[lane];
    float wo0 = w_out[0 * 32 + lane];
    float wo1 = w_out[1 * 32 + lane];
    float wo2 = w_out[2 * 32 + lane];
    float bo0 = b_out[0], bo1 = b_out[1], bo2 = b_out[2];

    // t = 0: h = tanh(Wih2 @ y + bias)   (h0 = 0)
    float acc = bias;
    const float* yrow = g_y + bidx * 18;
#pragma unroll
    for (int k = 0; k < 18; k++) acc = fmaf(w_ih2[lane * 18 + k], yrow[k], acc);
    float h = tanh_fast(acc);

    float* outp = out + (size_t)bidx * OUTL * DOUT;

    for (int t = 0; t < OUTL; t++) {
        float p0 = wo0 * h, p1 = wo1 * h, p2 = wo2 * h;
#pragma unroll
        for (int off = 16; off; off >>= 1) {
            p0 += __shfl_xor_sync(0xffffffffu, p0, off);
            p1 += __shfl_xor_sync(0xffffffffu, p1, off);
            p2 += __shfl_xor_sync(0xffffffffu, p2, off);
        }
        if (lane == 0) {
            outp[t * 3 + 0] = p0 + bo0;
            outp[t * 3 + 1] = p1 + bo1;
            outp[t * 3 + 2] = p2 + bo2;
        }
        if (t < OUTL - 1) {
            float accn = bias;
#pragma unroll
            for (int j = 0; j < 32; j++)
                accn = fmaf(Wh[j], __shfl_sync(0xffffffffu, h, j), accn);
            h = tanh_fast(accn);
        }
    }
}

// ---------------------------------------------------------------------------
extern "C" void kernel_launch(void* const* d_in, const int* in_sizes, int n_in,
                              void* d_out, int out_size)
{
    const float* x      = (const float*)d_in[0];
    const float* w_ih_f = (const float*)d_in[1];
    const float* w_hh_f = (const float*)d_in[2];
    const float* b_ih_f = (const float*)d_in[3];
    const float* b_hh_f = (const float*)d_in[4];
    const float* w_ih_b = (const float*)d_in[5];
    const float* w_hh_b = (const float*)d_in[6];
    const float* b_ih_b = (const float*)d_in[7];
    const float* b_hh_b = (const float*)d_in[8];
    const float* w_ih2  = (const float*)d_in[9];
    const float* w_hh2  = (const float*)d_in[10];
    const float* b_ih2  = (const float*)d_in[11];
    const float* b_hh2  = (const float*)d_in[12];
    const float* w_out  = (const float*)d_in[13];
    const float* b_out  = (const float*)d_in[14];
    float* out = (float*)d_out;

    dim3 tg(BB / 32, TT / 32);
    transpose_kernel<<<tg, 256>>>(x);

    rnn1_kernel<<<128, 128>>>(w_ih_f, w_hh_f, b_ih_f, b_hh_f,
                              w_ih_b, w_hh_b, b_ih_b, b_hh_b);

    rnn2_kernel<<<1024, 128>>>(w_ih2, w_hh2, b_ih2, b_hh2, w_out, b_out, out);
}